// round 1
// baseline (speedup 1.0000x reference)
#include <cuda_runtime.h>
#include <math.h>

// ConvPolicy14: tiny conv/deconv policy net, batch=1, N_LINKS=7.
// Entire network fused into one kernel, one warp. All weights staged to SMEM
// up-front (MLP-overlapped), intermediates live in SMEM, __syncwarp between
// stages. Latency-bound nanokernel.

#define NL 7

// SMEM weight segment offsets (cumulative)
#define W1  0      // conv1_w   (4,12,3) = 144
#define B1  144    // conv1_b   4
#define W2  148    // conv2_w   (4,4,3)  = 48
#define B2  196    // 4
#define W3  200    // conv3_w   (4,4,3)  = 48
#define B3  248    // 4
#define W4  252    // conv4_w   (3,4,3)  = 36
#define B4  288    // 3
#define D1W 291    // deconv1_w (3,4,3)  = 36
#define D1B 327    // 4
#define D2W 331    // deconv2_w (8,4,3)  = 96
#define D2B 427    // 4
#define D3W 431    // deconv3_w (8,4,3)  = 96
#define D3B 527    // 4
#define D4W 531    // deconv4_w (16,6,3) = 288
#define D4B 819    // 6
#define WTOT 825

__global__ void __launch_bounds__(32, 1)
convpolicy14_kernel(
    const float* __restrict__ x,
    const float* __restrict__ w1, const float* __restrict__ b1,
    const float* __restrict__ w2, const float* __restrict__ b2,
    const float* __restrict__ w3, const float* __restrict__ b3,
    const float* __restrict__ w4, const float* __restrict__ b4,
    const float* __restrict__ dw1, const float* __restrict__ db1,
    const float* __restrict__ dw2, const float* __restrict__ db2,
    const float* __restrict__ dw3, const float* __restrict__ db3,
    const float* __restrict__ dw4, const float* __restrict__ db4,
    float* __restrict__ out)
{
    const int tid = threadIdx.x;

    __shared__ float W[WTOT];
    __shared__ float jcat[12][7];
    __shared__ float ext[3];
    __shared__ float c1[4][7];
    __shared__ float c2[4][7];
    __shared__ float c2ds[4][3];
    __shared__ float c3[4][3];
    __shared__ float comb[3];
    __shared__ float dc1[4][3];
    __shared__ float dc2[4][3];
    __shared__ float dc2us[4][7];
    __shared__ float dc3[4][7];

    // ---- Stage 0a: stage ALL weights to SMEM (MLP-overlapped LDGs) ----
    {
        const float* srcs[16] = {w1,b1,w2,b2,w3,b3,w4,b4,
                                 dw1,db1,dw2,db2,dw3,db3,dw4,db4};
        const int    szs [16] = {144,4,48,4,48,4,36,3,36,4,96,4,96,4,288,6};
        int off = 0;
        #pragma unroll
        for (int s = 0; s < 16; s++) {
            const float* src = srcs[s];
            const int sz = szs[s];
            for (int i = tid; i < sz; i += 32)
                W[off + i] = src[i];
            off += sz;
        }
    }

    // ---- Stage 0b: build jcat (12,7) from x; ext_obs ----
    // jl  = concat([0,0], x[7:47])  -> (6,7) row-major
    // jdl = concat([0,0], x[53:93]) -> (6,7)
    for (int idx = tid; idx < 84; idx += 32) {
        int half = idx / 42;       // 0: jl, 1: jdl
        int r    = idx % 42;       // c*7 + l
        float v = 0.f;
        if (r >= 2) v = (half == 0) ? x[7 + r - 2] : x[53 + r - 2];
        jcat[half * 6 + r / 7][r % 7] = v;
    }
    if (tid == 0) {
        float qw = x[3], qx = x[4], qy = x[5], qz = x[6];
        ext[0] = atan2f(qz, qw) - atan2f(-qx, qy);
        ext[1] = x[47];   // obsd[0,0]
        ext[2] = x[52];   // obsd[0,5]
    }
    __syncwarp();

    // ---- Stage 1: conv1 (12->4 ch, k=3, pad=1, L=7) + tanh ----
    if (tid < 28) {
        int o = tid / 7, p = tid % 7;
        float acc = W[B1 + o];
        #pragma unroll
        for (int i = 0; i < 12; i++) {
            #pragma unroll
            for (int k = 0; k < 3; k++) {
                int q = p + k - 1;
                if (q >= 0 && q < 7)
                    acc += jcat[i][q] * W[W1 + (o * 12 + i) * 3 + k];
            }
        }
        c1[o][p] = tanhf(acc);
    }
    __syncwarp();

    // ---- Stage 2: conv2 (4->4, k=3, pad=1, L=7) + tanh ----
    if (tid < 28) {
        int o = tid / 7, p = tid % 7;
        float acc = W[B2 + o];
        #pragma unroll
        for (int i = 0; i < 4; i++) {
            #pragma unroll
            for (int k = 0; k < 3; k++) {
                int q = p + k - 1;
                if (q >= 0 && q < 7)
                    acc += c1[i][q] * W[W2 + (o * 4 + i) * 3 + k];
            }
        }
        c2[o][p] = tanhf(acc);
    }
    __syncwarp();

    // ---- Stage 3: downsample means over [0:3],[2:5],[4:7] ----
    if (tid < 12) {
        int o = tid / 3, j = tid % 3;
        c2ds[o][j] = (c2[o][2*j] + c2[o][2*j+1] + c2[o][2*j+2]) * (1.f / 3.f);
    }
    __syncwarp();

    // ---- Stage 4: conv3 (4->4, k=3, pad=1, L=3) + tanh ----
    if (tid < 12) {
        int o = tid / 3, p = tid % 3;
        float acc = W[B3 + o];
        #pragma unroll
        for (int i = 0; i < 4; i++) {
            #pragma unroll
            for (int k = 0; k < 3; k++) {
                int q = p + k - 1;
                if (q >= 0 && q < 3)
                    acc += c2ds[i][q] * W[W3 + (o * 4 + i) * 3 + k];
            }
        }
        c3[o][p] = tanhf(acc);
    }
    __syncwarp();

    // ---- Stage 5: conv4 (4->3, k=3, pad=0, L=3 -> 1) + tanh + ext ----
    if (tid < 3) {
        int o = tid;
        float acc = W[B4 + o];
        #pragma unroll
        for (int i = 0; i < 4; i++)
            #pragma unroll
            for (int k = 0; k < 3; k++)
                acc += c3[i][k] * W[W4 + (o * 4 + i) * 3 + k];
        comb[o] = tanhf(acc) + ext[o];
    }
    __syncwarp();

    // ---- Stage 6: deconv1 (3->4, k=3, pad=0, L=1 -> 3) + tanh ----
    // y[o][p] = sum_i comb[i] * w[i][o][p]
    if (tid < 12) {
        int o = tid / 3, p = tid % 3;
        float acc = W[D1B + o];
        #pragma unroll
        for (int i = 0; i < 3; i++)
            acc += comb[i] * W[D1W + (i * 4 + o) * 3 + p];
        dc1[o][p] = tanhf(acc);
    }
    __syncwarp();

    // ---- Stage 7: deconv2 (8->4, k=3, pad=1, L=3 -> 3) + tanh ----
    // input = concat([dc1, c3]); y[o][p] += x[i][t] w[i][o][k], t = p - k + 1
    if (tid < 12) {
        int o = tid / 3, p = tid % 3;
        float acc = W[D2B + o];
        #pragma unroll
        for (int i = 0; i < 8; i++) {
            #pragma unroll
            for (int k = 0; k < 3; k++) {
                int t = p - k + 1;
                if (t >= 0 && t < 3) {
                    float xv = (i < 4) ? dc1[i][t] : c3[i - 4][t];
                    acc += xv * W[D2W + (i * 4 + o) * 3 + k];
                }
            }
        }
        dc2[o][p] = tanhf(acc);
    }
    __syncwarp();

    // ---- Stage 8: upsample [0,0,0,1,1,2,2] ----
    if (tid < 28) {
        int o = tid / 7, p = tid % 7;
        const int m[7] = {0, 0, 0, 1, 1, 2, 2};
        dc2us[o][p] = dc2[o][m[p]];
    }
    __syncwarp();

    // ---- Stage 9: deconv3 (8->4, k=3, pad=1, L=7 -> 7) + tanh ----
    // input = concat([dc2us, c2])
    if (tid < 28) {
        int o = tid / 7, p = tid % 7;
        float acc = W[D3B + o];
        #pragma unroll
        for (int i = 0; i < 8; i++) {
            #pragma unroll
            for (int k = 0; k < 3; k++) {
                int t = p - k + 1;
                if (t >= 0 && t < 7) {
                    float xv = (i < 4) ? dc2us[i][t] : c2[i - 4][t];
                    acc += xv * W[D3W + (i * 4 + o) * 3 + k];
                }
            }
        }
        dc3[o][p] = tanhf(acc);
    }
    __syncwarp();

    // ---- Stage 10: deconv4 (16->6, k=3, pad=1, L=7 -> 7), no tanh ----
    // input = concat([dc3, jcat]); out = flat[2:]
    for (int idx = tid; idx < 42; idx += 32) {
        int o = idx / 7, p = idx % 7;
        float acc = W[D4B + o];
        #pragma unroll
        for (int i = 0; i < 16; i++) {
            #pragma unroll
            for (int k = 0; k < 3; k++) {
                int t = p - k + 1;
                if (t >= 0 && t < 7) {
                    float xv = (i < 4) ? dc3[i][t] : jcat[i - 4][t];
                    acc += xv * W[D4W + (i * 6 + o) * 3 + k];
                }
            }
        }
        int flat = o * 7 + p;
        if (flat >= 2) out[flat - 2] = acc;
    }
}

extern "C" void kernel_launch(void* const* d_in, const int* in_sizes, int n_in,
                              void* d_out, int out_size) {
    const float* x   = (const float*)d_in[0];
    const float* w1  = (const float*)d_in[1];
    const float* b1  = (const float*)d_in[2];
    const float* w2  = (const float*)d_in[3];
    const float* b2  = (const float*)d_in[4];
    const float* w3  = (const float*)d_in[5];
    const float* b3  = (const float*)d_in[6];
    const float* w4  = (const float*)d_in[7];
    const float* b4  = (const float*)d_in[8];
    const float* dw1 = (const float*)d_in[9];
    const float* db1 = (const float*)d_in[10];
    const float* dw2 = (const float*)d_in[11];
    const float* db2 = (const float*)d_in[12];
    const float* dw3 = (const float*)d_in[13];
    const float* db3 = (const float*)d_in[14];
    const float* dw4 = (const float*)d_in[15];
    const float* db4 = (const float*)d_in[16];
    float* out = (float*)d_out;

    convpolicy14_kernel<<<1, 32>>>(x, w1, b1, w2, b2, w3, b3, w4, b4,
                                   dw1, db1, dw2, db2, dw3, db3, dw4, db4, out);
}

// round 2
// speedup vs baseline: 1.4706x; 1.4706x over previous
#include <cuda_runtime.h>
#include <math.h>
#include <stdint.h>

// ConvPolicy14: tiny conv/deconv policy net, batch=1, N_LINKS=7.
// One kernel, one warp. Weights staged via cp.async (2 groups, overlapped with
// stage-1 compute). Fast tanh (expf+rcp). Down/upsample fused into convs.

// SMEM weight offsets (floats), all multiples of 4 for 16B cp.async alignment
#define W1  0      // (4,12,3) 144
#define B1  144    // 4
#define W2  148    // 48
#define B2  196    // 4
#define W3  200    // 48
#define B3  248    // 4
#define W4  252    // 36
#define B4  288    // 3 (pad to 292)
#define D1W 292    // 36
#define D1B 328    // 4
#define D2W 332    // 96
#define D2B 428    // 4
#define D3W 432    // 96
#define D3B 528    // 4
#define D4W 532    // 288
#define D4B 820    // 6 (pad to 828)
#define WTOT 828

__device__ __forceinline__ void cp16(uint32_t dst, const void* src) {
    asm volatile("cp.async.ca.shared.global [%0], [%1], 16;\n" :: "r"(dst), "l"(src));
}
__device__ __forceinline__ void cp4(uint32_t dst, const void* src) {
    asm volatile("cp.async.ca.shared.global [%0], [%1], 4;\n" :: "r"(dst), "l"(src));
}
__device__ __forceinline__ void cp_commit() {
    asm volatile("cp.async.commit_group;\n");
}
template<int N> __device__ __forceinline__ void cp_wait() {
    asm volatile("cp.async.wait_group %0;\n" :: "n"(N));
}

__device__ __forceinline__ float ftanh(float v) {
    // tanh(v) = 1 - 2/(exp(2v)+1); __expf+__fdividef => 2 MUFU + few FMA,
    // rel err ~1e-6, saturates correctly at +-1.
    float e = __expf(2.0f * v);
    return 1.0f - __fdividef(2.0f, e + 1.0f);
}

__global__ void __launch_bounds__(32, 1)
convpolicy14_kernel(
    const float* __restrict__ x,
    const float* __restrict__ w1, const float* __restrict__ b1,
    const float* __restrict__ w2, const float* __restrict__ b2,
    const float* __restrict__ w3, const float* __restrict__ b3,
    const float* __restrict__ w4, const float* __restrict__ b4,
    const float* __restrict__ dw1, const float* __restrict__ db1,
    const float* __restrict__ dw2, const float* __restrict__ db2,
    const float* __restrict__ dw3, const float* __restrict__ db3,
    const float* __restrict__ dw4, const float* __restrict__ db4,
    float* __restrict__ out)
{
    const int tid = threadIdx.x;

    __shared__ float W[WTOT];
    __shared__ float jcat[12][7];
    __shared__ float ext[3];
    __shared__ float c1[4][7];
    __shared__ float c2[4][7];
    __shared__ float c3[4][3];
    __shared__ float comb[3];
    __shared__ float dc1[4][3];
    __shared__ float dc2[4][3];
    __shared__ float dc3[4][7];

    const uint32_t sW = (uint32_t)__cvta_generic_to_shared(W);

    // ---- Group A: conv1 weights (needed first) ----
    // w1: 144 floats = 36 float4 ; b1: 4 floats = 1 float4
    {
        if (tid < 32) {
            // 36 float4 of w1: threads 0..31 take i=tid, threads 0..3 also i=32+tid
            cp16(sW + (W1 + tid * 4) * 4, (const float4*)w1 + tid);
            if (tid < 4) cp16(sW + (W1 + (32 + tid) * 4) * 4, (const float4*)w1 + 32 + tid);
            if (tid == 0) cp16(sW + B1 * 4, (const float4*)b1);
        }
        cp_commit();
    }

    // ---- Group B: everything else ----
    {
        // vector-copy helper pattern per segment (sz % 4 == 0)
        #define CPSEG(off, src, sz) \
            for (int i = tid; i < (sz) / 4; i += 32) \
                cp16(sW + ((off) + i * 4) * 4, (const float4*)(src) + i);
        CPSEG(W2, w2, 48)   if (tid == 31) cp16(sW + B2 * 4, (const float4*)b2);
        CPSEG(W3, w3, 48)   if (tid == 30) cp16(sW + B3 * 4, (const float4*)b3);
        CPSEG(W4, w4, 36)
        if (tid == 29) { cp4(sW + (B4+0)*4, b4+0); }
        if (tid == 28) { cp4(sW + (B4+1)*4, b4+1); }
        if (tid == 27) { cp4(sW + (B4+2)*4, b4+2); }
        CPSEG(D1W, dw1, 36) if (tid == 26) cp16(sW + D1B * 4, (const float4*)db1);
        CPSEG(D2W, dw2, 96) if (tid == 25) cp16(sW + D2B * 4, (const float4*)db2);
        CPSEG(D3W, dw3, 96) if (tid == 24) cp16(sW + D3B * 4, (const float4*)db3);
        CPSEG(D4W, dw4, 288)
        if (tid == 23) cp16(sW + D4B * 4, (const float4*)db4);       // db4[0..3]
        if (tid == 22) { cp4(sW + (D4B+4)*4, db4+4); }
        if (tid == 21) { cp4(sW + (D4B+5)*4, db4+5); }
        #undef CPSEG
        cp_commit();
    }

    // ---- Build jcat (12,7) + ext while weights fly ----
    for (int idx = tid; idx < 84; idx += 32) {
        int half = idx / 42;       // 0: jl, 1: jdl
        int r    = idx % 42;       // c*7 + l
        float v = 0.f;
        if (r >= 2) v = (half == 0) ? x[7 + r - 2] : x[53 + r - 2];
        jcat[half * 6 + r / 7][r % 7] = v;
    }
    if (tid == 0) {
        float qw = x[3], qx = x[4], qy = x[5], qz = x[6];
        ext[0] = atan2f(qz, qw) - atan2f(-qx, qy);
        ext[1] = x[47];
        ext[2] = x[52];
    }

    // Wait for group A (conv1 weights); group B may still be in flight.
    cp_wait<1>();
    __syncwarp();

    // ---- Stage 1: conv1 (12->4, k=3, pad=1, L=7) + tanh ----
    if (tid < 28) {
        int o = tid / 7, p = tid % 7;
        float a0 = W[B1 + o], a1 = 0.f, a2 = 0.f;
        #pragma unroll
        for (int i = 0; i < 12; i++) {
            #pragma unroll
            for (int k = 0; k < 3; k++) {
                int q = p + k - 1;
                if (q >= 0 && q < 7) {
                    float t = jcat[i][q] * W[W1 + (o * 12 + i) * 3 + k];
                    if (i % 3 == 0) a0 += t; else if (i % 3 == 1) a1 += t; else a2 += t;
                }
            }
        }
        c1[o][p] = ftanh(a0 + a1 + a2);
    }
    cp_wait<0>();   // rest of weights now resident
    __syncwarp();

    // ---- Stage 2: conv2 (4->4, k=3, pad=1, L=7) + tanh ----
    if (tid < 28) {
        int o = tid / 7, p = tid % 7;
        float a0 = W[B2 + o], a1 = 0.f;
        #pragma unroll
        for (int i = 0; i < 4; i++) {
            #pragma unroll
            for (int k = 0; k < 3; k++) {
                int q = p + k - 1;
                if (q >= 0 && q < 7) {
                    float t = c1[i][q] * W[W2 + (o * 4 + i) * 3 + k];
                    if (i & 1) a1 += t; else a0 += t;
                }
            }
        }
        c2[o][p] = ftanh(a0 + a1);
    }
    __syncwarp();

    // ---- Stage 3+4 fused: downsample-mean inline + conv3 (4->4,k=3,pad=1,L=3) ----
    if (tid < 12) {
        int o = tid / 3, p = tid % 3;
        float a0 = W[B3 + o], a1 = 0.f;
        #pragma unroll
        for (int i = 0; i < 4; i++) {
            #pragma unroll
            for (int k = 0; k < 3; k++) {
                int q = p + k - 1;
                if (q >= 0 && q < 3) {
                    float ds = (c2[i][2*q] + c2[i][2*q+1] + c2[i][2*q+2]) * (1.f/3.f);
                    float t = ds * W[W3 + (o * 4 + i) * 3 + k];
                    if (i & 1) a1 += t; else a0 += t;
                }
            }
        }
        c3[o][p] = ftanh(a0 + a1);
    }
    __syncwarp();

    // ---- Stage 5: conv4 (4->3, k=3, pad=0, L=3->1) + tanh + ext ----
    if (tid < 3) {
        int o = tid;
        float a0 = W[B4 + o], a1 = 0.f;
        #pragma unroll
        for (int i = 0; i < 4; i++)
            #pragma unroll
            for (int k = 0; k < 3; k++) {
                float t = c3[i][k] * W[W4 + (o * 4 + i) * 3 + k];
                if (i & 1) a1 += t; else a0 += t;
            }
        comb[o] = ftanh(a0 + a1) + ext[o];
    }
    __syncwarp();

    // ---- Stage 6: deconv1 (3->4, k=3, pad=0, L=1->3) + tanh ----
    if (tid < 12) {
        int o = tid / 3, p = tid % 3;
        float acc = W[D1B + o];
        #pragma unroll
        for (int i = 0; i < 3; i++)
            acc += comb[i] * W[D1W + (i * 4 + o) * 3 + p];
        dc1[o][p] = ftanh(acc);
    }
    __syncwarp();

    // ---- Stage 7: deconv2 (8->4, k=3, pad=1, L=3->3) + tanh ----
    if (tid < 12) {
        int o = tid / 3, p = tid % 3;
        float a0 = W[D2B + o], a1 = 0.f;
        #pragma unroll
        for (int i = 0; i < 8; i++) {
            #pragma unroll
            for (int k = 0; k < 3; k++) {
                int t = p - k + 1;
                if (t >= 0 && t < 3) {
                    float xv = (i < 4) ? dc1[i][t] : c3[i - 4][t];
                    float m = xv * W[D2W + (i * 4 + o) * 3 + k];
                    if (i & 1) a1 += m; else a0 += m;
                }
            }
        }
        dc2[o][p] = ftanh(a0 + a1);
    }
    __syncwarp();

    // ---- Stage 8+9 fused: upsample [0,0,0,1,1,2,2] inline + deconv3 ----
    if (tid < 28) {
        int o = tid / 7, p = tid % 7;
        float a0 = W[D3B + o], a1 = 0.f;
        #pragma unroll
        for (int i = 0; i < 8; i++) {
            #pragma unroll
            for (int k = 0; k < 3; k++) {
                int t = p - k + 1;
                if (t >= 0 && t < 7) {
                    int tu = (t < 3) ? 0 : ((t < 5) ? 1 : 2);   // upsample map
                    float xv = (i < 4) ? dc2[i][tu] : c2[i - 4][t];
                    float m = xv * W[D3W + (i * 4 + o) * 3 + k];
                    if (i & 1) a1 += m; else a0 += m;
                }
            }
        }
        dc3[o][p] = ftanh(a0 + a1);
    }
    __syncwarp();

    // ---- Stage 10: deconv4 (16->6, k=3, pad=1, L=7->7), linear; out = flat[2:] ----
    for (int idx = tid; idx < 42; idx += 32) {
        int o = idx / 7, p = idx % 7;
        float a0 = W[D4B + o], a1 = 0.f, a2 = 0.f, a3 = 0.f;
        #pragma unroll
        for (int i = 0; i < 16; i++) {
            #pragma unroll
            for (int k = 0; k < 3; k++) {
                int t = p - k + 1;
                if (t >= 0 && t < 7) {
                    float xv = (i < 4) ? dc3[i][t] : jcat[i - 4][t];
                    float m = xv * W[D4W + (i * 6 + o) * 3 + k];
                    switch (i & 3) {
                        case 0: a0 += m; break;
                        case 1: a1 += m; break;
                        case 2: a2 += m; break;
                        default: a3 += m; break;
                    }
                }
            }
        }
        int flat = o * 7 + p;
        if (flat >= 2) out[flat - 2] = (a0 + a1) + (a2 + a3);
    }
}

extern "C" void kernel_launch(void* const* d_in, const int* in_sizes, int n_in,
                              void* d_out, int out_size) {
    const float* x   = (const float*)d_in[0];
    const float* w1  = (const float*)d_in[1];
    const float* b1  = (const float*)d_in[2];
    const float* w2  = (const float*)d_in[3];
    const float* b2  = (const float*)d_in[4];
    const float* w3  = (const float*)d_in[5];
    const float* b3  = (const float*)d_in[6];
    const float* w4  = (const float*)d_in[7];
    const float* b4  = (const float*)d_in[8];
    const float* dw1 = (const float*)d_in[9];
    const float* db1 = (const float*)d_in[10];
    const float* dw2 = (const float*)d_in[11];
    const float* db2 = (const float*)d_in[12];
    const float* dw3 = (const float*)d_in[13];
    const float* db3 = (const float*)d_in[14];
    const float* dw4 = (const float*)d_in[15];
    const float* db4 = (const float*)d_in[16];
    float* out = (float*)d_out;

    convpolicy14_kernel<<<1, 32>>>(x, w1, b1, w2, b2, w3, b3, w4, b4,
                                   dw1, db1, dw2, db2, dw3, db3, dw4, db4, out);
}

// round 3
// speedup vs baseline: 1.4760x; 1.0037x over previous
#include <cuda_runtime.h>
#include <math.h>
#include <stdint.h>

// ConvPolicy14: tiny conv/deconv policy net, batch=1, N_LINKS=7.
// One kernel, one warp. Weights staged via cp.async (3 groups, pipelined
// against compute stages). MUFU.TANH activations. BAR.SYNC (3cyc @ nw=1)
// instead of WARPSYNC (~23cyc) at stage boundaries.

// SMEM weight offsets (floats), all multiples of 4 for 16B cp.async alignment
#define W1  0      // (4,12,3) 144
#define B1  144    // 4
#define W2  148    // 48
#define B2  196    // 4
#define W3  200    // 48
#define B3  248    // 4
#define W4  252    // 36
#define B4  288    // 3 (pad to 292)
#define D1W 292    // 36
#define D1B 328    // 4
#define D2W 332    // 96
#define D2B 428    // 4
#define D3W 432    // 96
#define D3B 528    // 4
#define D4W 532    // 288
#define D4B 820    // 6 (pad to 828)
#define WTOT 828

__device__ __forceinline__ void cp16(uint32_t dst, const void* src) {
    asm volatile("cp.async.ca.shared.global [%0], [%1], 16;\n" :: "r"(dst), "l"(src));
}
__device__ __forceinline__ void cp4(uint32_t dst, const void* src) {
    asm volatile("cp.async.ca.shared.global [%0], [%1], 4;\n" :: "r"(dst), "l"(src));
}
__device__ __forceinline__ void cp_commit() {
    asm volatile("cp.async.commit_group;\n");
}
template<int N> __device__ __forceinline__ void cp_wait() {
    asm volatile("cp.async.wait_group %0;\n" :: "n"(N));
}

__device__ __forceinline__ float ftanh(float v) {
    float r;
    asm("tanh.approx.f32 %0, %1;" : "=f"(r) : "f"(v));   // MUFU.TANH, lat~16
    return r;
}

__global__ void __launch_bounds__(32, 1)
convpolicy14_kernel(
    const float* __restrict__ x,
    const float* __restrict__ w1, const float* __restrict__ b1,
    const float* __restrict__ w2, const float* __restrict__ b2,
    const float* __restrict__ w3, const float* __restrict__ b3,
    const float* __restrict__ w4, const float* __restrict__ b4,
    const float* __restrict__ dw1, const float* __restrict__ db1,
    const float* __restrict__ dw2, const float* __restrict__ db2,
    const float* __restrict__ dw3, const float* __restrict__ db3,
    const float* __restrict__ dw4, const float* __restrict__ db4,
    float* __restrict__ out)
{
    const int tid = threadIdx.x;

    __shared__ float W[WTOT];
    __shared__ float jcat[12][7];
    __shared__ float ext[3];
    __shared__ float c1[4][7];
    __shared__ float c2[4][7];
    __shared__ float c3[4][3];
    __shared__ float comb[3];
    __shared__ float dc1[4][3];
    __shared__ float dc2[4][3];
    __shared__ float dc3[4][7];

    const uint32_t sW = (uint32_t)__cvta_generic_to_shared(W);

    // ---- Group A: conv1 weights (needed first) ----
    {
        cp16(sW + (W1 + tid * 4) * 4, (const float4*)w1 + tid);           // 32 of 36
        if (tid < 4) cp16(sW + (W1 + (32 + tid) * 4) * 4, (const float4*)w1 + 32 + tid);
        if (tid == 0) cp16(sW + B1 * 4, (const float4*)b1);
        cp_commit();
    }

    #define CPSEG(off, src, sz) \
        for (int i = tid; i < (sz) / 4; i += 32) \
            cp16(sW + ((off) + i * 4) * 4, (const float4*)(src) + i);

    // ---- Group B1: stage 2-6 weights (conv2..conv4, deconv1) ----
    {
        CPSEG(W2, w2, 48)   if (tid == 31) cp16(sW + B2 * 4, (const float4*)b2);
        CPSEG(W3, w3, 48)   if (tid == 30) cp16(sW + B3 * 4, (const float4*)b3);
        CPSEG(W4, w4, 36)
        if (tid == 29) { cp4(sW + (B4+0)*4, b4+0); }
        if (tid == 28) { cp4(sW + (B4+1)*4, b4+1); }
        if (tid == 27) { cp4(sW + (B4+2)*4, b4+2); }
        CPSEG(D1W, dw1, 36) if (tid == 26) cp16(sW + D1B * 4, (const float4*)db1);
        cp_commit();
    }

    // ---- Group B2: deconv2..deconv4 weights ----
    {
        CPSEG(D2W, dw2, 96) if (tid == 25) cp16(sW + D2B * 4, (const float4*)db2);
        CPSEG(D3W, dw3, 96) if (tid == 24) cp16(sW + D3B * 4, (const float4*)db3);
        CPSEG(D4W, dw4, 288)
        if (tid == 23) cp16(sW + D4B * 4, (const float4*)db4);       // db4[0..3]
        if (tid == 22) { cp4(sW + (D4B+4)*4, db4+4); }
        if (tid == 21) { cp4(sW + (D4B+5)*4, db4+5); }
        cp_commit();
    }
    #undef CPSEG

    // ---- Build jcat (12,7) + ext while weights fly ----
    for (int idx = tid; idx < 84; idx += 32) {
        int half = idx / 42;       // 0: jl, 1: jdl
        int r    = idx % 42;       // c*7 + l
        float v = 0.f;
        if (r >= 2) v = (half == 0) ? x[7 + r - 2] : x[53 + r - 2];
        jcat[half * 6 + r / 7][r % 7] = v;
    }
    if (tid == 0) {
        float qw = x[3], qx = x[4], qy = x[5], qz = x[6];
        ext[0] = atan2f(qz, qw) - atan2f(-qx, qy);
        ext[1] = x[47];
        ext[2] = x[52];
    }

    cp_wait<2>();          // group A resident
    __syncthreads();       // BAR.SYNC: 3cyc @ 1 warp (also orders jcat STS)

    // ---- Stage 1: conv1 (12->4, k=3, pad=1, L=7) + tanh ----
    if (tid < 28) {
        int o = tid / 7, p = tid % 7;
        float a0 = W[B1 + o], a1 = 0.f, a2 = 0.f;
        #pragma unroll
        for (int i = 0; i < 12; i++) {
            #pragma unroll
            for (int k = 0; k < 3; k++) {
                int q = p + k - 1;
                if (q >= 0 && q < 7) {
                    float t = jcat[i][q] * W[W1 + (o * 12 + i) * 3 + k];
                    if (i % 3 == 0) a0 += t; else if (i % 3 == 1) a1 += t; else a2 += t;
                }
            }
        }
        c1[o][p] = ftanh(a0 + a1 + a2);
    }
    cp_wait<1>();          // group B1 resident (stage 2-6 weights)
    __syncthreads();

    // ---- Stage 2: conv2 (4->4, k=3, pad=1, L=7) + tanh ----
    if (tid < 28) {
        int o = tid / 7, p = tid % 7;
        float a0 = W[B2 + o], a1 = 0.f;
        #pragma unroll
        for (int i = 0; i < 4; i++) {
            #pragma unroll
            for (int k = 0; k < 3; k++) {
                int q = p + k - 1;
                if (q >= 0 && q < 7) {
                    float t = c1[i][q] * W[W2 + (o * 4 + i) * 3 + k];
                    if (i & 1) a1 += t; else a0 += t;
                }
            }
        }
        c2[o][p] = ftanh(a0 + a1);
    }
    __syncthreads();

    // ---- Stage 3+4 fused: downsample-mean inline + conv3 (4->4,k=3,pad=1,L=3) ----
    if (tid < 12) {
        int o = tid / 3, p = tid % 3;
        float a0 = W[B3 + o], a1 = 0.f;
        #pragma unroll
        for (int i = 0; i < 4; i++) {
            #pragma unroll
            for (int k = 0; k < 3; k++) {
                int q = p + k - 1;
                if (q >= 0 && q < 3) {
                    float ds = (c2[i][2*q] + c2[i][2*q+1] + c2[i][2*q+2]) * (1.f/3.f);
                    float t = ds * W[W3 + (o * 4 + i) * 3 + k];
                    if (i & 1) a1 += t; else a0 += t;
                }
            }
        }
        c3[o][p] = ftanh(a0 + a1);
    }
    __syncthreads();

    // ---- Stage 5: conv4 (4->3, k=3, pad=0, L=3->1) + tanh + ext ----
    if (tid < 3) {
        int o = tid;
        float a0 = W[B4 + o], a1 = 0.f;
        #pragma unroll
        for (int i = 0; i < 4; i++)
            #pragma unroll
            for (int k = 0; k < 3; k++) {
                float t = c3[i][k] * W[W4 + (o * 4 + i) * 3 + k];
                if (i & 1) a1 += t; else a0 += t;
            }
        comb[o] = ftanh(a0 + a1) + ext[o];
    }
    __syncthreads();

    // ---- Stage 6: deconv1 (3->4, k=3, pad=0, L=1->3) + tanh ----
    if (tid < 12) {
        int o = tid / 3, p = tid % 3;
        float acc = W[D1B + o];
        #pragma unroll
        for (int i = 0; i < 3; i++)
            acc += comb[i] * W[D1W + (i * 4 + o) * 3 + p];
        dc1[o][p] = ftanh(acc);
    }
    cp_wait<0>();          // group B2 resident (deconv2..4 weights)
    __syncthreads();

    // ---- Stage 7: deconv2 (8->4, k=3, pad=1, L=3->3) + tanh ----
    if (tid < 12) {
        int o = tid / 3, p = tid % 3;
        float a0 = W[D2B + o], a1 = 0.f;
        #pragma unroll
        for (int i = 0; i < 8; i++) {
            #pragma unroll
            for (int k = 0; k < 3; k++) {
                int t = p - k + 1;
                if (t >= 0 && t < 3) {
                    float xv = (i < 4) ? dc1[i][t] : c3[i - 4][t];
                    float m = xv * W[D2W + (i * 4 + o) * 3 + k];
                    if (i & 1) a1 += m; else a0 += m;
                }
            }
        }
        dc2[o][p] = ftanh(a0 + a1);
    }
    __syncthreads();

    // ---- Stage 8+9 fused: upsample [0,0,0,1,1,2,2] inline + deconv3 ----
    if (tid < 28) {
        int o = tid / 7, p = tid % 7;
        float a0 = W[D3B + o], a1 = 0.f;
        #pragma unroll
        for (int i = 0; i < 8; i++) {
            #pragma unroll
            for (int k = 0; k < 3; k++) {
                int t = p - k + 1;
                if (t >= 0 && t < 7) {
                    int tu = (t < 3) ? 0 : ((t < 5) ? 1 : 2);   // upsample map
                    float xv = (i < 4) ? dc2[i][tu] : c2[i - 4][t];
                    float m = xv * W[D3W + (i * 4 + o) * 3 + k];
                    if (i & 1) a1 += m; else a0 += m;
                }
            }
        }
        dc3[o][p] = ftanh(a0 + a1);
    }
    __syncthreads();

    // ---- Stage 10: deconv4 (16->6, k=3, pad=1, L=7->7), linear; out = flat[2:] ----
    for (int idx = tid; idx < 42; idx += 32) {
        int o = idx / 7, p = idx % 7;
        float a0 = W[D4B + o], a1 = 0.f, a2 = 0.f, a3 = 0.f;
        #pragma unroll
        for (int i = 0; i < 16; i++) {
            #pragma unroll
            for (int k = 0; k < 3; k++) {
                int t = p - k + 1;
                if (t >= 0 && t < 7) {
                    float xv = (i < 4) ? dc3[i][t] : jcat[i - 4][t];
                    float m = xv * W[D4W + (i * 6 + o) * 3 + k];
                    switch (i & 3) {
                        case 0: a0 += m; break;
                        case 1: a1 += m; break;
                        case 2: a2 += m; break;
                        default: a3 += m; break;
                    }
                }
            }
        }
        int flat = o * 7 + p;
        if (flat >= 2) out[flat - 2] = (a0 + a1) + (a2 + a3);
    }
}

extern "C" void kernel_launch(void* const* d_in, const int* in_sizes, int n_in,
                              void* d_out, int out_size) {
    const float* x   = (const float*)d_in[0];
    const float* w1  = (const float*)d_in[1];
    const float* b1  = (const float*)d_in[2];
    const float* w2  = (const float*)d_in[3];
    const float* b2  = (const float*)d_in[4];
    const float* w3  = (const float*)d_in[5];
    const float* b3  = (const float*)d_in[6];
    const float* w4  = (const float*)d_in[7];
    const float* b4  = (const float*)d_in[8];
    const float* dw1 = (const float*)d_in[9];
    const float* db1 = (const float*)d_in[10];
    const float* dw2 = (const float*)d_in[11];
    const float* db2 = (const float*)d_in[12];
    const float* dw3 = (const float*)d_in[13];
    const float* db3 = (const float*)d_in[14];
    const float* dw4 = (const float*)d_in[15];
    const float* db4 = (const float*)d_in[16];
    float* out = (float*)d_out;

    convpolicy14_kernel<<<1, 32>>>(x, w1, b1, w2, b2, w3, b3, w4, b4,
                                   dw1, db1, dw2, db2, dw3, db3, dw4, db4, out);
}

// round 4
// speedup vs baseline: 1.8605x; 1.2605x over previous
#include <cuda_runtime.h>
#include <math.h>
#include <stdint.h>

// ConvPolicy14 nanonet. 2 warps: warp0 = compute only; warp1 = cp.async staging,
// ext (atan2), and weight repack into padded o-major layout for LDS.128.
// Ghost-zero activation borders make all conv/deconv loops guard-free.

// ---- raw staged weight offsets (floats) ----
#define W1r  0      // (4,12,3) 144
#define B1r  144
#define W2r  148
#define B2r  196
#define W3r  200
#define B3r  248
#define W4r  252
#define B4r  288    // 3
#define D1Wr 292
#define D1Br 328
#define D2Wr 332
#define D2Br 428
#define D3Wr 432
#define D3Br 528
#define D4Wr 532
#define D4Br 820    // 6

// ---- padded repacked offsets (floats, 16B-aligned blocks) ----
#define PW1 0      // [4][12][4] = 192
#define PW2 192    // [4][4][4]  = 64
#define PW3 256    // 64
#define PW4 320    // [3][4][4]  = 48
#define PD1 368    // [4][3][4]  = 48   (transposed from (3,4,3))
#define PD2 416    // [4][8][4]  = 128
#define PD3 544    // 128
#define PD4 672    // [6][16][4] = 384
#define PTOT 1056

// ---- ghosted activation offsets within ACT (floats) ----
// all rows have 1 zero ghost col each side
#define JG(i,c)   ACT[(i)*9+(c)]         // 12 rows x 9  (valid cols 1..7)
#define C1G(i,c)  ACT[108+(i)*9+(c)]
#define C2G(i,c)  ACT[144+(i)*9+(c)]
#define DSG(i,c)  ACT[180+(i)*5+(c)]     // 4 rows x 5 (valid 1..3)
#define C3G(i,c)  ACT[200+(i)*5+(c)]
#define DC1G(i,c) ACT[220+(i)*5+(c)]
#define DC2G(i,c) ACT[240+(i)*5+(c)]
#define UG(i,c)   ACT[260+(i)*9+(c)]
#define DC3G(i,c) ACT[296+(i)*9+(c)]     // -> 332
#define COMB(i)   ACT[332+(i)]
#define EXT(i)    ACT[336+(i)]
#define ACT_F4    88                     // 352 floats zeroed as float4

__device__ __forceinline__ void cp16(uint32_t dst, const void* src) {
    asm volatile("cp.async.ca.shared.global [%0], [%1], 16;\n" :: "r"(dst), "l"(src));
}
__device__ __forceinline__ void cp4(uint32_t dst, const void* src) {
    asm volatile("cp.async.ca.shared.global [%0], [%1], 4;\n" :: "r"(dst), "l"(src));
}
__device__ __forceinline__ void cp_commit() { asm volatile("cp.async.commit_group;\n"); }
template<int N> __device__ __forceinline__ void cp_wait() {
    asm volatile("cp.async.wait_group %0;\n" :: "n"(N));
}
__device__ __forceinline__ float ftanh(float v) {
    float r; asm("tanh.approx.f32 %0, %1;" : "=f"(r) : "f"(v)); return r;
}

__global__ void __launch_bounds__(64, 1)
convpolicy14_kernel(
    const float* __restrict__ x,
    const float* __restrict__ w1, const float* __restrict__ b1,
    const float* __restrict__ w2, const float* __restrict__ b2,
    const float* __restrict__ w3, const float* __restrict__ b3,
    const float* __restrict__ w4, const float* __restrict__ b4,
    const float* __restrict__ dw1, const float* __restrict__ db1,
    const float* __restrict__ dw2, const float* __restrict__ db2,
    const float* __restrict__ dw3, const float* __restrict__ db3,
    const float* __restrict__ dw4, const float* __restrict__ db4,
    float* __restrict__ out)
{
    const int tid = threadIdx.x;
    const int warp = tid >> 5;
    const int t1 = tid & 31;

    __shared__ __align__(16) float RAW[832];
    __shared__ __align__(16) float PAD[PTOT];
    __shared__ __align__(16) float ACT[352];

    const uint32_t sR = (uint32_t)__cvta_generic_to_shared(RAW);

    if (warp == 1) {
        // ---------- producer warp ----------
        // Group A: conv1 weights + bias
        cp16(sR + (W1r + t1 * 4) * 4, (const float4*)w1 + t1);
        if (t1 < 4) cp16(sR + (W1r + (32 + t1) * 4) * 4, (const float4*)w1 + 32 + t1);
        if (t1 == 0) cp16(sR + B1r * 4, (const float4*)b1);
        cp_commit();

        #define CPSEG(off, src, sz) \
            for (int i = t1; i < (sz) / 4; i += 32) \
                cp16(sR + ((off) + i * 4) * 4, (const float4*)(src) + i);
        // Group B1: conv2..conv4, deconv1
        CPSEG(W2r, w2, 48)    if (t1 == 31) cp16(sR + B2r * 4, (const float4*)b2);
        CPSEG(W3r, w3, 48)    if (t1 == 30) cp16(sR + B3r * 4, (const float4*)b3);
        CPSEG(W4r, w4, 36)
        if (t1 == 29) cp4(sR + (B4r+0)*4, b4+0);
        if (t1 == 28) cp4(sR + (B4r+1)*4, b4+1);
        if (t1 == 27) cp4(sR + (B4r+2)*4, b4+2);
        CPSEG(D1Wr, dw1, 36)  if (t1 == 26) cp16(sR + D1Br * 4, (const float4*)db1);
        cp_commit();
        // Group B2: deconv2..deconv4
        CPSEG(D2Wr, dw2, 96)  if (t1 == 25) cp16(sR + D2Br * 4, (const float4*)db2);
        CPSEG(D3Wr, dw3, 96)  if (t1 == 24) cp16(sR + D3Br * 4, (const float4*)db3);
        CPSEG(D4Wr, dw4, 288)
        if (t1 == 23) cp16(sR + D4Br * 4, (const float4*)db4);
        if (t1 == 22) cp4(sR + (D4Br+4)*4, db4+4);
        if (t1 == 21) cp4(sR + (D4Br+5)*4, db4+5);
        cp_commit();
        #undef CPSEG

        // ext while weights fly
        if (t1 == 0) {
            float qw = x[3], qx = x[4], qy = x[5], qz = x[6];
            EXT(0) = atan2f(qz, qw) - atan2f(-qx, qy);
            EXT(1) = x[47];
            EXT(2) = x[52];
        }

        cp_wait<2>();
        __syncwarp();
        // repack conv1: pair j = o*12+i, raw stride 3 -> padded stride 4
        for (int j = t1; j < 48; j += 32) {
            float a = RAW[W1r + j*3], b = RAW[W1r + j*3+1], c = RAW[W1r + j*3+2];
            *(float4*)&PAD[PW1 + j*4] = make_float4(a, b, c, 0.f);
        }
    } else {
        // ---------- compute warp: zero ghosts + build jcat ----------
        for (int j = t1; j < ACT_F4; j += 32)
            *(float4*)&ACT[j*4] = make_float4(0.f, 0.f, 0.f, 0.f);
        __syncwarp();
        for (int idx = t1; idx < 84; idx += 32) {
            int half = idx / 42;
            int r    = idx % 42;
            float v = 0.f;
            if (r >= 2) v = (half == 0) ? x[7 + r - 2] : x[53 + r - 2];
            JG(half * 6 + r / 7, r % 7 + 1) = v;
        }
    }
    __syncthreads();   // bar1: PW1 ready

    if (warp == 0) {
        // ---- Stage 1: conv1 (12->4, pad=1, L=7) ----
        if (t1 < 28) {
            int o = t1 / 7, p = t1 % 7;
            float a0 = RAW[B1r + o], a1 = 0.f, a2 = 0.f;
            #pragma unroll
            for (int i = 0; i < 12; i++) {
                float4 w = *(const float4*)&PAD[PW1 + (o*12 + i)*4];
                a0 += JG(i, p+0) * w.x;
                a1 += JG(i, p+1) * w.y;
                a2 += JG(i, p+2) * w.z;
            }
            C1G(o, p+1) = ftanh(a0 + a1 + a2);
        }
    } else {
        cp_wait<1>();
        __syncwarp();
        for (int j = t1; j < 16; j += 32) {   // conv2
            float a = RAW[W2r + j*3], b = RAW[W2r + j*3+1], c = RAW[W2r + j*3+2];
            *(float4*)&PAD[PW2 + j*4] = make_float4(a, b, c, 0.f);
        }
        for (int j = t1; j < 16; j += 32) {   // conv3
            float a = RAW[W3r + j*3], b = RAW[W3r + j*3+1], c = RAW[W3r + j*3+2];
            *(float4*)&PAD[PW3 + j*4] = make_float4(a, b, c, 0.f);
        }
        for (int j = t1; j < 12; j += 32) {   // conv4
            float a = RAW[W4r + j*3], b = RAW[W4r + j*3+1], c = RAW[W4r + j*3+2];
            *(float4*)&PAD[PW4 + j*4] = make_float4(a, b, c, 0.f);
        }
        for (int j = t1; j < 12; j += 32) {   // deconv1: transpose (3,4,3) -> [o][i][4]
            int o = j / 3, i = j % 3;
            int s = (i*4 + o)*3;
            float a = RAW[D1Wr + s], b = RAW[D1Wr + s+1], c = RAW[D1Wr + s+2];
            *(float4*)&PAD[PD1 + j*4] = make_float4(a, b, c, 0.f);
        }
    }
    __syncthreads();   // bar2: stage2-6 weights + ext ready

    if (warp == 0) {
        // ---- Stage 2: conv2 (4->4, pad=1, L=7) ----
        if (t1 < 28) {
            int o = t1 / 7, p = t1 % 7;
            float a0 = RAW[B2r + o], a1 = 0.f, a2 = 0.f;
            #pragma unroll
            for (int i = 0; i < 4; i++) {
                float4 w = *(const float4*)&PAD[PW2 + (o*4 + i)*4];
                a0 += C1G(i, p+0) * w.x;
                a1 += C1G(i, p+1) * w.y;
                a2 += C1G(i, p+2) * w.z;
            }
            C2G(o, p+1) = ftanh(a0 + a1 + a2);
        }
        __syncwarp();
        // ---- Stage 3: downsample means ----
        if (t1 < 12) {
            int o = t1 / 3, j = t1 % 3;
            DSG(o, j+1) = (C2G(o, 2*j+1) + C2G(o, 2*j+2) + C2G(o, 2*j+3)) * (1.f/3.f);
        }
        __syncwarp();
        // ---- Stage 4: conv3 (4->4, pad=1, L=3) ----
        if (t1 < 12) {
            int o = t1 / 3, p = t1 % 3;
            float a0 = RAW[B3r + o], a1 = 0.f, a2 = 0.f;
            #pragma unroll
            for (int i = 0; i < 4; i++) {
                float4 w = *(const float4*)&PAD[PW3 + (o*4 + i)*4];
                a0 += DSG(i, p+0) * w.x;
                a1 += DSG(i, p+1) * w.y;
                a2 += DSG(i, p+2) * w.z;
            }
            C3G(o, p+1) = ftanh(a0 + a1 + a2);
        }
        __syncwarp();
        // ---- Stage 5: conv4 (4->3, pad=0, L=3->1) + ext ----
        if (t1 < 3) {
            int o = t1;
            float a0 = RAW[B4r + o], a1 = 0.f, a2 = 0.f;
            #pragma unroll
            for (int i = 0; i < 4; i++) {
                float4 w = *(const float4*)&PAD[PW4 + (o*4 + i)*4];
                a0 += C3G(i, 1) * w.x;
                a1 += C3G(i, 2) * w.y;
                a2 += C3G(i, 3) * w.z;
            }
            COMB(o) = ftanh(a0 + a1 + a2) + EXT(o);
        }
        __syncwarp();
        // ---- Stage 6: deconv1 (3->4, pad=0, L=1->3) ----
        if (t1 < 12) {
            int o = t1 / 3, p = t1 % 3;
            float acc = RAW[D1Br + o];
            #pragma unroll
            for (int i = 0; i < 3; i++)
                acc += COMB(i) * PAD[PD1 + (o*3 + i)*4 + p];
            DC1G(o, p+1) = ftanh(acc);
        }
    } else {
        cp_wait<0>();
        __syncwarp();
        for (int j = t1; j < 32; j += 32) {   // deconv2: (8,4,3) -> [o=4][i=8][4]
            int o = j / 8, i = j % 8;
            int s = (i*4 + o)*3;
            float a = RAW[D2Wr + s], b = RAW[D2Wr + s+1], c = RAW[D2Wr + s+2];
            *(float4*)&PAD[PD2 + j*4] = make_float4(a, b, c, 0.f);
        }
        for (int j = t1; j < 32; j += 32) {   // deconv3
            int o = j / 8, i = j % 8;
            int s = (i*4 + o)*3;
            float a = RAW[D3Wr + s], b = RAW[D3Wr + s+1], c = RAW[D3Wr + s+2];
            *(float4*)&PAD[PD3 + j*4] = make_float4(a, b, c, 0.f);
        }
        for (int j = t1; j < 96; j += 32) {   // deconv4: (16,6,3) -> [o=6][i=16][4]
            int o = j / 16, i = j % 16;
            int s = (i*6 + o)*3;
            float a = RAW[D4Wr + s], b = RAW[D4Wr + s+1], c = RAW[D4Wr + s+2];
            *(float4*)&PAD[PD4 + j*4] = make_float4(a, b, c, 0.f);
        }
    }
    __syncthreads();   // bar3: deconv weights ready

    if (warp == 0) {
        // ---- Stage 7: deconv2 (8->4, pad=1, L=3) ----
        // y[o][p] = sum_i  in[p-k+1] w[k];  ghost idx: k=0 -> p+2, k=1 -> p+1, k=2 -> p
        if (t1 < 12) {
            int o = t1 / 3, p = t1 % 3;
            float a0 = RAW[D2Br + o], a1 = 0.f, a2 = 0.f;
            #pragma unroll
            for (int i = 0; i < 8; i++) {
                float4 w = *(const float4*)&PAD[PD2 + (o*8 + i)*4];
                float v0 = (i < 4) ? DC1G(i, p+2) : C3G(i-4, p+2);
                float v1 = (i < 4) ? DC1G(i, p+1) : C3G(i-4, p+1);
                float v2 = (i < 4) ? DC1G(i, p+0) : C3G(i-4, p+0);
                a0 += v0 * w.x;
                a1 += v1 * w.y;
                a2 += v2 * w.z;
            }
            DC2G(o, p+1) = ftanh(a0 + a1 + a2);
        }
        __syncwarp();
        // ---- Stage 8: upsample [0,0,0,1,1,2,2] ----
        if (t1 < 28) {
            int o = t1 / 7, p = t1 % 7;
            int m = (p < 3) ? 0 : ((p < 5) ? 1 : 2);
            UG(o, p+1) = DC2G(o, m+1);
        }
        __syncwarp();
        // ---- Stage 9: deconv3 (8->4, pad=1, L=7) ----
        if (t1 < 28) {
            int o = t1 / 7, p = t1 % 7;
            float a0 = RAW[D3Br + o], a1 = 0.f, a2 = 0.f;
            #pragma unroll
            for (int i = 0; i < 8; i++) {
                float4 w = *(const float4*)&PAD[PD3 + (o*8 + i)*4];
                float v0 = (i < 4) ? UG(i, p+2) : C2G(i-4, p+2);
                float v1 = (i < 4) ? UG(i, p+1) : C2G(i-4, p+1);
                float v2 = (i < 4) ? UG(i, p+0) : C2G(i-4, p+0);
                a0 += v0 * w.x;
                a1 += v1 * w.y;
                a2 += v2 * w.z;
            }
            DC3G(o, p+1) = ftanh(a0 + a1 + a2);
        }
    }
    __syncthreads();   // bar4: dc3 ready, both warps do final stage

    // ---- Stage 10: deconv4 (16->6, pad=1, L=7), linear; out = flat[2:] ----
    if (tid < 42) {
        int o = tid / 7, p = tid % 7;
        float a0 = RAW[D4Br + o], a1 = 0.f, a2 = 0.f;
        #pragma unroll
        for (int i = 0; i < 16; i++) {
            float4 w = *(const float4*)&PAD[PD4 + (o*16 + i)*4];
            float v0 = (i < 4) ? DC3G(i, p+2) : JG(i-4, p+2);
            float v1 = (i < 4) ? DC3G(i, p+1) : JG(i-4, p+1);
            float v2 = (i < 4) ? DC3G(i, p+0) : JG(i-4, p+0);
            a0 += v0 * w.x;
            a1 += v1 * w.y;
            a2 += v2 * w.z;
        }
        int flat = o * 7 + p;
        if (flat >= 2) out[flat - 2] = (a0 + a1) + a2;
    }
}

extern "C" void kernel_launch(void* const* d_in, const int* in_sizes, int n_in,
                              void* d_out, int out_size) {
    const float* x   = (const float*)d_in[0];
    const float* w1  = (const float*)d_in[1];
    const float* b1  = (const float*)d_in[2];
    const float* w2  = (const float*)d_in[3];
    const float* b2  = (const float*)d_in[4];
    const float* w3  = (const float*)d_in[5];
    const float* b3  = (const float*)d_in[6];
    const float* w4  = (const float*)d_in[7];
    const float* b4  = (const float*)d_in[8];
    const float* dw1 = (const float*)d_in[9];
    const float* db1 = (const float*)d_in[10];
    const float* dw2 = (const float*)d_in[11];
    const float* db2 = (const float*)d_in[12];
    const float* dw3 = (const float*)d_in[13];
    const float* db3 = (const float*)d_in[14];
    const float* dw4 = (const float*)d_in[15];
    const float* db4 = (const float*)d_in[16];
    float* out = (float*)d_out;

    convpolicy14_kernel<<<1, 64>>>(x, w1, b1, w2, b2, w3, b3, w4, b4,
                                   dw1, db1, dw2, db2, dw3, db3, dw4, db4, out);
}

// round 6
// speedup vs baseline: 1.9231x; 1.0337x over previous
#include <cuda_runtime.h>
#include <math.h>
#include <stdint.h>

// ConvPolicy14 nanonet. 4 warps: warp0 computes; warps 1-3 stage+repack all
// weights in parallel via direct LDG->STS (one hop). One global barrier before
// compute, one before the final wide stage. Ghost-zero activation borders;
// fused conv4+deconv1; upsample fused into deconv3; branchless bias gather
// (32 floats in warp2 lanes 0..31; 3 stragglers on warp1 lanes 1..3).

// ---- padded repacked weight offsets (floats, 16B blocks) ----
#define PW1 0      // [4][12][4] = 192
#define PW2 192    // [4][4][4]  = 64
#define PW3 256    // 64
#define PW4 320    // [3][4][4]  = 48
#define PD1 368    // [4][3][4]  = 48  (transposed from (3,4,3))
#define PD2 416    // [4][8][4]  = 128
#define PD3 544    // 128
#define PD4 672    // [6][16][4] = 384
#define PTOT 1056

// ---- bias/ext SMEM (compact), not zeroed ----
// b1@0(4) b2@4(4) b3@8(4) b4@12(3) db1@15(4) db2@19(4) db3@23(4) db4@27(6) ext@36(3)
#define BB1  0
#define BB2  4
#define BB3  8
#define BB4  12
#define BDB1 15
#define BDB2 19
#define BDB3 23
#define BDB4 27
#define BEXT 36
#define BTOT 40

// ---- ghosted activations (zeroed). rows have 1 ghost col each side ----
#define JG(i,c)   ACT[(i)*9+(c)]          // 12 x 9, valid cols 1..7
#define C1G(i,c)  ACT[108+(i)*9+(c)]      // 4 x 9
#define C2G(i,c)  ACT[144+(i)*9+(c)]      // 4 x 9
#define DSG(i,c)  ACT[180+(i)*5+(c)]      // 4 x 5, valid 1..3
#define C3G(i,c)  ACT[200+(i)*5+(c)]      // 4 x 5
#define DC1G(i,c) ACT[220+(i)*5+(c)]      // 4 x 5
#define DC2G(i,c) ACT[240+(i)*5+(c)]      // 4 x 5
#define DC3G(i,c) ACT[260+(i)*9+(c)]      // 4 x 9 -> 296
#define ACT_F4    74                      // 296 floats

__device__ __forceinline__ float ftanh(float v) {
    float r; asm("tanh.approx.f32 %0, %1;" : "=f"(r) : "f"(v)); return r;
}

__global__ void __launch_bounds__(128, 1)
convpolicy14_kernel(
    const float* __restrict__ x,
    const float* __restrict__ w1, const float* __restrict__ b1,
    const float* __restrict__ w2, const float* __restrict__ b2,
    const float* __restrict__ w3, const float* __restrict__ b3,
    const float* __restrict__ w4, const float* __restrict__ b4,
    const float* __restrict__ dw1, const float* __restrict__ db1,
    const float* __restrict__ dw2, const float* __restrict__ db2,
    const float* __restrict__ dw3, const float* __restrict__ db3,
    const float* __restrict__ dw4, const float* __restrict__ db4,
    float* __restrict__ out)
{
    const int tid  = threadIdx.x;
    const int warp = tid >> 5;
    const int t1   = tid & 31;

    __shared__ __align__(16) float PAD[PTOT];
    __shared__ __align__(16) float BIA[BTOT];
    __shared__ __align__(16) float ACT[296];

    if (warp == 1) {
        // conv1: 48 triples, already o-major (4,12,3)
        for (int j = t1; j < 48; j += 32) {
            float a = __ldg(w1 + j*3), b = __ldg(w1 + j*3 + 1), c = __ldg(w1 + j*3 + 2);
            *(float4*)&PAD[PW1 + j*4] = make_float4(a, b, c, 0.f);
        }
        // deconv4 first half: j = o*16+i, src (16,6,3): s=(i*6+o)*3
        for (int j = t1; j < 48; j += 32) {
            int o = j / 16, i = j % 16, s = (i*6 + o)*3;
            float a = __ldg(dw4 + s), b = __ldg(dw4 + s + 1), c = __ldg(dw4 + s + 2);
            *(float4*)&PAD[PD4 + j*4] = make_float4(a, b, c, 0.f);
        }
        // stragglers: ext0 (atan2), db4[5], ext1, ext2
        if (t1 == 0) {
            float qw = __ldg(x+3), qx = __ldg(x+4), qy = __ldg(x+5), qz = __ldg(x+6);
            BIA[BEXT + 0] = atan2f(qz, qw) - atan2f(-qx, qy);
        } else if (t1 == 1) {
            BIA[BDB4 + 5] = __ldg(db4 + 5);
        } else if (t1 == 2) {
            BIA[BEXT + 1] = __ldg(x + 47);
        } else if (t1 == 3) {
            BIA[BEXT + 2] = __ldg(x + 52);
        }
    } else if (warp == 2) {
        if (t1 < 16) {  // conv2, conv3 (o-major)
            {
                float a = __ldg(w2 + t1*3), b = __ldg(w2 + t1*3 + 1), c = __ldg(w2 + t1*3 + 2);
                *(float4*)&PAD[PW2 + t1*4] = make_float4(a, b, c, 0.f);
            }
            {
                float a = __ldg(w3 + t1*3), b = __ldg(w3 + t1*3 + 1), c = __ldg(w3 + t1*3 + 2);
                *(float4*)&PAD[PW3 + t1*4] = make_float4(a, b, c, 0.f);
            }
        }
        if (t1 < 12) {  // conv4 (o-major), deconv1 (transpose (3,4,3) -> [o][i])
            {
                float a = __ldg(w4 + t1*3), b = __ldg(w4 + t1*3 + 1), c = __ldg(w4 + t1*3 + 2);
                *(float4*)&PAD[PW4 + t1*4] = make_float4(a, b, c, 0.f);
            }
            {
                int o = t1 / 3, i = t1 % 3, s = (i*4 + o)*3;
                float a = __ldg(dw1 + s), b = __ldg(dw1 + s + 1), c = __ldg(dw1 + s + 2);
                *(float4*)&PAD[PD1 + t1*4] = make_float4(a, b, c, 0.f);
            }
        }
        // branchless bias gather: BIA[0..31] = b1,b2,b3,b4,db1,db2,db3,db4[0..4]
        {
            const float* s = b1; int off = t1;
            if (t1 >= 4)  { s = b2;  off = t1 - 4;  }
            if (t1 >= 8)  { s = b3;  off = t1 - 8;  }
            if (t1 >= 12) { s = b4;  off = t1 - 12; }
            if (t1 >= 15) { s = db1; off = t1 - 15; }
            if (t1 >= 19) { s = db2; off = t1 - 19; }
            if (t1 >= 23) { s = db3; off = t1 - 23; }
            if (t1 >= 27) { s = db4; off = t1 - 27; }
            BIA[t1] = __ldg(s + off);
        }
    } else if (warp == 3) {
        {   // deconv2: j=o*8+i, src (8,4,3): s=(i*4+o)*3
            int o = t1 / 8, i = t1 % 8, s = (i*4 + o)*3;
            float a = __ldg(dw2 + s), b = __ldg(dw2 + s + 1), c = __ldg(dw2 + s + 2);
            *(float4*)&PAD[PD2 + t1*4] = make_float4(a, b, c, 0.f);
        }
        {   // deconv3
            int o = t1 / 8, i = t1 % 8, s = (i*4 + o)*3;
            float a = __ldg(dw3 + s), b = __ldg(dw3 + s + 1), c = __ldg(dw3 + s + 2);
            *(float4*)&PAD[PD3 + t1*4] = make_float4(a, b, c, 0.f);
        }
        for (int j = 48 + t1; j < 96; j += 32) {   // deconv4 second half
            int o = j / 16, i = j % 16, s = (i*6 + o)*3;
            float a = __ldg(dw4 + s), b = __ldg(dw4 + s + 1), c = __ldg(dw4 + s + 2);
            *(float4*)&PAD[PD4 + j*4] = make_float4(a, b, c, 0.f);
        }
    } else {
        // warp0: zero ghosted ACT, build jcat
        for (int j = t1; j < ACT_F4; j += 32)
            *(float4*)&ACT[j*4] = make_float4(0.f, 0.f, 0.f, 0.f);
        __syncwarp();
        for (int idx = t1; idx < 84; idx += 32) {
            int half = idx / 42;
            int r    = idx % 42;
            float v = 0.f;
            if (r >= 2) v = (half == 0) ? __ldg(x + 7 + r - 2) : __ldg(x + 53 + r - 2);
            JG(half * 6 + r / 7, r % 7 + 1) = v;
        }
    }
    __syncthreads();   // bar1: ALL weights/biases/ext + jcat ready

    if (warp == 0) {
        // ---- Stage 1: conv1 (12->4, pad=1, L=7) ----
        if (t1 < 28) {
            int o = t1 / 7, p = t1 % 7;
            float a0 = BIA[BB1 + o], a1 = 0.f, a2 = 0.f;
            #pragma unroll
            for (int i = 0; i < 12; i++) {
                float4 w = *(const float4*)&PAD[PW1 + (o*12 + i)*4];
                a0 += JG(i, p+0) * w.x;
                a1 += JG(i, p+1) * w.y;
                a2 += JG(i, p+2) * w.z;
            }
            C1G(o, p+1) = ftanh(a0 + a1 + a2);
        }
        __syncwarp();

        // ---- Stage 2: conv2 (4->4, pad=1, L=7) ----
        if (t1 < 28) {
            int o = t1 / 7, p = t1 % 7;
            float a0 = BIA[BB2 + o], a1 = 0.f, a2 = 0.f;
            #pragma unroll
            for (int i = 0; i < 4; i++) {
                float4 w = *(const float4*)&PAD[PW2 + (o*4 + i)*4];
                a0 += C1G(i, p+0) * w.x;
                a1 += C1G(i, p+1) * w.y;
                a2 += C1G(i, p+2) * w.z;
            }
            C2G(o, p+1) = ftanh(a0 + a1 + a2);
        }
        __syncwarp();

        // ---- Stage 3: downsample means ----
        if (t1 < 12) {
            int o = t1 / 3, j = t1 % 3;
            DSG(o, j+1) = (C2G(o, 2*j+1) + C2G(o, 2*j+2) + C2G(o, 2*j+3)) * (1.f/3.f);
        }
        __syncwarp();

        // ---- Stage 4: conv3 (4->4, pad=1, L=3) ----
        if (t1 < 12) {
            int o = t1 / 3, p = t1 % 3;
            float a0 = BIA[BB3 + o], a1 = 0.f, a2 = 0.f;
            #pragma unroll
            for (int i = 0; i < 4; i++) {
                float4 w = *(const float4*)&PAD[PW3 + (o*4 + i)*4];
                a0 += DSG(i, p+0) * w.x;
                a1 += DSG(i, p+1) * w.y;
                a2 += DSG(i, p+2) * w.z;
            }
            C3G(o, p+1) = ftanh(a0 + a1 + a2);
        }
        __syncwarp();

        // ---- Stage 5+6 fused: conv4 (4->3, L=3->1) + ext, then deconv1 (3->4, L=1->3) ----
        if (t1 < 12) {
            int o = t1 / 3, p = t1 % 3;
            float cv[12];
            #pragma unroll
            for (int i = 0; i < 4; i++) {
                cv[i*3+0] = C3G(i, 1);
                cv[i*3+1] = C3G(i, 2);
                cv[i*3+2] = C3G(i, 3);
            }
            float comb[3];
            #pragma unroll
            for (int j = 0; j < 3; j++) {
                float a0 = BIA[BB4 + j], a1 = 0.f, a2 = 0.f;
                #pragma unroll
                for (int i = 0; i < 4; i++) {
                    float4 w = *(const float4*)&PAD[PW4 + (j*4 + i)*4];
                    a0 += cv[i*3+0] * w.x;
                    a1 += cv[i*3+1] * w.y;
                    a2 += cv[i*3+2] * w.z;
                }
                comb[j] = ftanh(a0 + a1 + a2) + BIA[BEXT + j];
            }
            float acc = BIA[BDB1 + o];
            #pragma unroll
            for (int j = 0; j < 3; j++)
                acc += comb[j] * PAD[PD1 + (o*3 + j)*4 + p];
            DC1G(o, p+1) = ftanh(acc);
        }
        __syncwarp();

        // ---- Stage 7: deconv2 (8->4, pad=1, L=3) ----
        if (t1 < 12) {
            int o = t1 / 3, p = t1 % 3;
            float a0 = BIA[BDB2 + o], a1 = 0.f, a2 = 0.f;
            #pragma unroll
            for (int i = 0; i < 8; i++) {
                float4 w = *(const float4*)&PAD[PD2 + (o*8 + i)*4];
                float v0 = (i < 4) ? DC1G(i, p+2) : C3G(i-4, p+2);
                float v1 = (i < 4) ? DC1G(i, p+1) : C3G(i-4, p+1);
                float v2 = (i < 4) ? DC1G(i, p+0) : C3G(i-4, p+0);
                a0 += v0 * w.x;
                a1 += v1 * w.y;
                a2 += v2 * w.z;
            }
            DC2G(o, p+1) = ftanh(a0 + a1 + a2);
        }
        __syncwarp();

        // ---- Stage 9: deconv3 (8->4, pad=1, L=7) with upsample fused ----
        // k=0,1,2 -> t = p-k+1; DC2G col: t<0 -> ghost0, t>6 -> ghost4,
        // else upsample-map um(t)+1 (um: 0,0,0,1,1,2,2). C2G col: t+1 = p-k+2.
        if (t1 < 28) {
            int o = t1 / 7, p = t1 % 7;
            int cu[3];
            #pragma unroll
            for (int k = 0; k < 3; k++) {
                int t = p - k + 1;
                cu[k] = (t < 0) ? 0 : ((t > 6) ? 4 : ((t < 3) ? 1 : ((t < 5) ? 2 : 3)));
            }
            float a0 = BIA[BDB3 + o], a1 = 0.f, a2 = 0.f;
            #pragma unroll
            for (int i = 0; i < 8; i++) {
                float4 w = *(const float4*)&PAD[PD3 + (o*8 + i)*4];
                float v0 = (i < 4) ? DC2G(i, cu[0]) : C2G(i-4, p+2);
                float v1 = (i < 4) ? DC2G(i, cu[1]) : C2G(i-4, p+1);
                float v2 = (i < 4) ? DC2G(i, cu[2]) : C2G(i-4, p+0);
                a0 += v0 * w.x;
                a1 += v1 * w.y;
                a2 += v2 * w.z;
            }
            DC3G(o, p+1) = ftanh(a0 + a1 + a2);
        }
    }
    __syncthreads();   // bar2: dc3 ready

    // ---- Stage 10: deconv4 (16->6, pad=1, L=7), linear; out = flat[2:] ----
    if (tid < 42) {
        int o = tid / 7, p = tid % 7;
        float a0 = BIA[BDB4 + o], a1 = 0.f, a2 = 0.f;
        #pragma unroll
        for (int i = 0; i < 16; i++) {
            float4 w = *(const float4*)&PAD[PD4 + (o*16 + i)*4];
            float v0 = (i < 4) ? DC3G(i, p+2) : JG(i-4, p+2);
            float v1 = (i < 4) ? DC3G(i, p+1) : JG(i-4, p+1);
            float v2 = (i < 4) ? DC3G(i, p+0) : JG(i-4, p+0);
            a0 += v0 * w.x;
            a1 += v1 * w.y;
            a2 += v2 * w.z;
        }
        int flat = o * 7 + p;
        if (flat >= 2) out[flat - 2] = (a0 + a1) + a2;
    }
}

extern "C" void kernel_launch(void* const* d_in, const int* in_sizes, int n_in,
                              void* d_out, int out_size) {
    const float* x   = (const float*)d_in[0];
    const float* w1  = (const float*)d_in[1];
    const float* b1  = (const float*)d_in[2];
    const float* w2  = (const float*)d_in[3];
    const float* b2  = (const float*)d_in[4];
    const float* w3  = (const float*)d_in[5];
    const float* b3  = (const float*)d_in[6];
    const float* w4  = (const float*)d_in[7];
    const float* b4  = (const float*)d_in[8];
    const float* dw1 = (const float*)d_in[9];
    const float* db1 = (const float*)d_in[10];
    const float* dw2 = (const float*)d_in[11];
    const float* db2 = (const float*)d_in[12];
    const float* dw3 = (const float*)d_in[13];
    const float* db3 = (const float*)d_in[14];
    const float* dw4 = (const float*)d_in[15];
    const float* db4 = (const float*)d_in[16];
    float* out = (float*)d_out;

    convpolicy14_kernel<<<1, 128>>>(x, w1, b1, w2, b2, w3, b3, w4, b4,
                                    dw1, db1, dw2, db2, dw3, db3, dw4, db4, out);
}